// round 3
// baseline (speedup 1.0000x reference)
#include <cuda_runtime.h>

// Problem constants
#define V_SZ   10000
#define IN_SZ  64
#define H_SZ   128
#define L_SEQ  64
#define T_TR   4096

#define VB     16                     // vocab rows per precompute block
#define NB_P   ((V_SZ + VB - 1) / VB) // 625
#define NB_D   125                    // partial-GEMV blocks
#define VPB_D  (V_SZ / NB_D)          // 80 vocab rows per GEMV block

// Scratch (no allocations allowed — __device__ globals)
__device__ float g_h2[V_SZ * H_SZ];        // per-vocab hidden_out
__device__ float g_energy[V_SZ];           // per-vocab attention energy
__device__ float g_coeff[V_SZ];            // summed softmax weight per vocab
__device__ float g_partials[NB_D * H_SZ];  // GEMV partials

typedef unsigned long long u64;

// packed f32x2 FMA (sm_100+): 2 fp32 MACs per instruction
__device__ __forceinline__ u64 fma2(u64 a, u64 b, u64 c) {
    u64 d;
    asm("fma.rn.f32x2 %0, %1, %2, %3;" : "=l"(d) : "l"(a), "l"(b), "l"(c));
    return d;
}
__device__ __forceinline__ float hsum2(u64 v) {
    float lo, hi;
    asm("mov.b64 {%0, %1}, %2;" : "=f"(lo), "=f"(hi) : "l"(v));
    return lo + hi;
}
// fast, accurate-enough (~1e-6) sigmoid / tanh via MUFU ex2 + rcp
__device__ __forceinline__ float sig_f(float x) {
    return __fdividef(1.0f, 1.0f + __expf(-x));
}
__device__ __forceinline__ float tanh_f(float x) {
    return 2.0f * sig_f(2.0f * x) - 1.0f;
}

// ---------------------------------------------------------------------------
// Kernel 0: zero the coefficient scatter buffer (graph replays need this)
// ---------------------------------------------------------------------------
__global__ void zero_coeff_kernel() {
    int i = blockIdx.x * blockDim.x + threadIdx.x;
    if (i < V_SZ) g_coeff[i] = 0.0f;
}

// ---------------------------------------------------------------------------
// Kernel 1: fused per-vocab precompute.
// Per vocab id v:  x = emb[v];
//   layer1: gates i,g,o (f is dead since c0=0) -> h1 = sig(o)*tanh(sig(i)*tanh(g))
//   layer2: same with K=128 -> h2  (stored to g_h2)
//   energy: relu(h2 @ Wp1^T + bp1) . Wp2 + bp2   (stored to g_energy)
// Block = 128 threads (thread owns output column h), VB=16 vocab rows/block,
// register sub-tiles of 4 rows; k-dim done with packed f32x2 FMAs.
// ---------------------------------------------------------------------------
__global__ __launch_bounds__(128) void precompute_kernel(
    const float* __restrict__ emb,
    const float* __restrict__ W1, const float* __restrict__ bi1, const float* __restrict__ bh1,
    const float* __restrict__ W2, const float* __restrict__ bi2, const float* __restrict__ bh2,
    const float* __restrict__ Wp1, const float* __restrict__ bp1,
    const float* __restrict__ Wp2, const float* __restrict__ bp2)
{
    __shared__ __align__(16) float xs[VB][IN_SZ];
    __shared__ __align__(16) float h1s[VB][H_SZ];
    __shared__ __align__(16) float h2s[VB][H_SZ];

    const int tid = threadIdx.x;
    const int v0  = blockIdx.x * VB;

    // load embedding rows (contiguous, fully coalesced)
    for (int i = tid; i < VB * IN_SZ; i += 128) {
        int v = v0 + (i >> 6);
        xs[i >> 6][i & 63] = (v < V_SZ) ? emb[v * IN_SZ + (i & 63)] : 0.0f;
    }
    __syncthreads();

    const int h = tid; // output column 0..127

    // ---------------- layer 1 (K = 64) ----------------
    {
        const float* Wi = W1 + h * IN_SZ;                 // i gate row
        const float* Wc = W1 + (2 * H_SZ + h) * IN_SZ;    // g (c_hat) row
        const float* Wo = W1 + (3 * H_SZ + h) * IN_SZ;    // o gate row
        const float bi = bi1[h] + bh1[h];
        const float bc = bi1[2 * H_SZ + h] + bh1[2 * H_SZ + h];
        const float bo = bi1[3 * H_SZ + h] + bh1[3 * H_SZ + h];

        for (int sb = 0; sb < VB; sb += 4) {
            u64 ai[4] = {0, 0, 0, 0}, ac[4] = {0, 0, 0, 0}, ao[4] = {0, 0, 0, 0};
            #pragma unroll 4
            for (int k = 0; k < IN_SZ; k += 4) {
                ulonglong2 wi = *(const ulonglong2*)(Wi + k);
                ulonglong2 wc = *(const ulonglong2*)(Wc + k);
                ulonglong2 wo = *(const ulonglong2*)(Wo + k);
                #pragma unroll
                for (int r = 0; r < 4; r++) {
                    ulonglong2 xv = *(const ulonglong2*)(&xs[sb + r][k]);
                    ai[r] = fma2(wi.x, xv.x, ai[r]); ai[r] = fma2(wi.y, xv.y, ai[r]);
                    ac[r] = fma2(wc.x, xv.x, ac[r]); ac[r] = fma2(wc.y, xv.y, ac[r]);
                    ao[r] = fma2(wo.x, xv.x, ao[r]); ao[r] = fma2(wo.y, xv.y, ao[r]);
                }
            }
            #pragma unroll
            for (int r = 0; r < 4; r++) {
                float gi = hsum2(ai[r]) + bi;
                float gc = hsum2(ac[r]) + bc;
                float go = hsum2(ao[r]) + bo;
                float c  = sig_f(gi) * tanh_f(gc);
                h1s[sb + r][h] = sig_f(go) * tanh_f(c);
            }
        }
    }
    __syncthreads();

    // ---------------- layer 2 (K = 128) ----------------
    {
        const float* Wi = W2 + h * H_SZ;
        const float* Wc = W2 + (2 * H_SZ + h) * H_SZ;
        const float* Wo = W2 + (3 * H_SZ + h) * H_SZ;
        const float bi = bi2[h] + bh2[h];
        const float bc = bi2[2 * H_SZ + h] + bh2[2 * H_SZ + h];
        const float bo = bi2[3 * H_SZ + h] + bh2[3 * H_SZ + h];

        for (int sb = 0; sb < VB; sb += 4) {
            u64 ai[4] = {0, 0, 0, 0}, ac[4] = {0, 0, 0, 0}, ao[4] = {0, 0, 0, 0};
            #pragma unroll 4
            for (int k = 0; k < H_SZ; k += 4) {
                ulonglong2 wi = *(const ulonglong2*)(Wi + k);
                ulonglong2 wc = *(const ulonglong2*)(Wc + k);
                ulonglong2 wo = *(const ulonglong2*)(Wo + k);
                #pragma unroll
                for (int r = 0; r < 4; r++) {
                    ulonglong2 xv = *(const ulonglong2*)(&h1s[sb + r][k]);
                    ai[r] = fma2(wi.x, xv.x, ai[r]); ai[r] = fma2(wi.y, xv.y, ai[r]);
                    ac[r] = fma2(wc.x, xv.x, ac[r]); ac[r] = fma2(wc.y, xv.y, ac[r]);
                    ao[r] = fma2(wo.x, xv.x, ao[r]); ao[r] = fma2(wo.y, xv.y, ao[r]);
                }
            }
            #pragma unroll
            for (int r = 0; r < 4; r++) {
                float gi = hsum2(ai[r]) + bi;
                float gc = hsum2(ac[r]) + bc;
                float go = hsum2(ao[r]) + bo;
                float c  = sig_f(gi) * tanh_f(gc);
                float h2 = sig_f(go) * tanh_f(c);
                h2s[sb + r][h] = h2;
                int v = v0 + sb + r;
                if (v < V_SZ) g_h2[v * H_SZ + h] = h2;
            }
        }
    }
    __syncthreads();

    // ---------------- attention energy ----------------
    // 4 warps, each warp handles 4 rows; lane handles units (lane, lane+32).
    const int warp = tid >> 5, lane = tid & 31;
    for (int rr = 0; rr < 4; rr++) {
        int row = warp * 4 + rr;
        int v   = v0 + row;
        float s = 0.0f;
        #pragma unroll
        for (int uu = 0; uu < 2; uu++) {
            int u = lane + uu * 32;
            const float* wr = Wp1 + u * H_SZ;
            float e = bp1[u];
            #pragma unroll 8
            for (int k = 0; k < H_SZ; k += 4) {
                float4 w4 = *(const float4*)(wr + k);
                float4 x4 = *(const float4*)(&h2s[row][k]);
                e = fmaf(w4.x, x4.x, e); e = fmaf(w4.y, x4.y, e);
                e = fmaf(w4.z, x4.z, e); e = fmaf(w4.w, x4.w, e);
            }
            e = fmaxf(e, 0.0f);
            s = fmaf(Wp2[u], e, s);
        }
        #pragma unroll
        for (int off = 16; off > 0; off >>= 1)
            s += __shfl_xor_sync(0xffffffffu, s, off);
        if (lane == 0 && v < V_SZ) g_energy[v] = s + bp2[0];
    }
}

// ---------------------------------------------------------------------------
// Kernel 2: per-trace softmax over gathered energies, scatter weights into
// per-vocab coefficients. One warp per trace (L=64 -> 2 positions per lane).
// ---------------------------------------------------------------------------
__global__ void softmax_scatter_kernel(const int* __restrict__ traces,
                                       const int* __restrict__ lengths)
{
    int gw   = (blockIdx.x * blockDim.x + threadIdx.x) >> 5;
    int lane = threadIdx.x & 31;
    if (gw >= T_TR) return;

    const int* tr = traces + gw * L_SEQ;
    int len = lengths[gw];
    int t0  = tr[lane];
    int t1  = tr[lane + 32];
    bool ok0 = lane < len;
    bool ok1 = (lane + 32) < len;

    float e0 = ok0 ? g_energy[t0] : -1e30f;
    float e1 = ok1 ? g_energy[t1] : -1e30f;

    float m = fmaxf(e0, e1);
    #pragma unroll
    for (int off = 16; off > 0; off >>= 1)
        m = fmaxf(m, __shfl_xor_sync(0xffffffffu, m, off));

    float x0 = ok0 ? __expf(e0 - m) : 0.0f;
    float x1 = ok1 ? __expf(e1 - m) : 0.0f;
    float s  = x0 + x1;
    #pragma unroll
    for (int off = 16; off > 0; off >>= 1)
        s += __shfl_xor_sync(0xffffffffu, s, off);

    float inv = 1.0f / s; // len >= 1 guarantees s > 0
    if (ok0) atomicAdd(&g_coeff[t0], x0 * inv);
    if (ok1) atomicAdd(&g_coeff[t1], x1 * inv);
}

// ---------------------------------------------------------------------------
// Kernel 3: partial GEMV  final[h] = sum_v coeff[v] * h2[v][h]
// ---------------------------------------------------------------------------
__global__ __launch_bounds__(128) void gemv_partial_kernel() {
    int b   = blockIdx.x;
    int tid = threadIdx.x;
    float acc = 0.0f;
    int vbeg = b * VPB_D;
    #pragma unroll 4
    for (int v = vbeg; v < vbeg + VPB_D; v++)
        acc = fmaf(g_coeff[v], g_h2[v * H_SZ + tid], acc);
    g_partials[b * H_SZ + tid] = acc;
}

// ---------------------------------------------------------------------------
// Kernel 4: reduce partials + output linear layer
// ---------------------------------------------------------------------------
__global__ __launch_bounds__(128) void finalize_kernel(
    const float* __restrict__ W_out, const float* __restrict__ b_out,
    float* __restrict__ out)
{
    __shared__ float fin[H_SZ];
    int tid = threadIdx.x;
    float f = 0.0f;
    for (int b = 0; b < NB_D; b++) f += g_partials[b * H_SZ + tid];
    fin[tid] = f;
    __syncthreads();

    float o = b_out[tid];
    const float* wr = W_out + tid * H_SZ;
    #pragma unroll 8
    for (int k = 0; k < H_SZ; k++) o = fmaf(wr[k], fin[k], o);
    out[tid] = o;
}

// ---------------------------------------------------------------------------
// Launch: inputs per metadata order:
// 0 emb, 1 W_ih1, 2 W_hh1, 3 b_ih1, 4 b_hh1, 5 W_ih2, 6 W_hh2, 7 b_ih2,
// 8 b_hh2, 9 Wp1, 10 bp1, 11 Wp2, 12 bp2, 13 W_out, 14 b_out,
// 15 traces(int32), 16 lengths(int32)
// ---------------------------------------------------------------------------
extern "C" void kernel_launch(void* const* d_in, const int* in_sizes, int n_in,
                              void* d_out, int out_size)
{
    const float* emb   = (const float*)d_in[0];
    const float* W1    = (const float*)d_in[1];
    const float* bi1   = (const float*)d_in[3];
    const float* bh1   = (const float*)d_in[4];
    const float* W2    = (const float*)d_in[5];
    const float* bi2   = (const float*)d_in[7];
    const float* bh2   = (const float*)d_in[8];
    const float* Wp1   = (const float*)d_in[9];
    const float* bp1   = (const float*)d_in[10];
    const float* Wp2   = (const float*)d_in[11];
    const float* bp2   = (const float*)d_in[12];
    const float* Wout  = (const float*)d_in[13];
    const float* bout  = (const float*)d_in[14];
    const int* traces  = (const int*)d_in[15];
    const int* lengths = (const int*)d_in[16];
    float* out = (float*)d_out;

    zero_coeff_kernel<<<(V_SZ + 255) / 256, 256>>>();
    precompute_kernel<<<NB_P, 128>>>(emb, W1, bi1, bh1, W2, bi2, bh2,
                                     Wp1, bp1, Wp2, bp2);
    softmax_scatter_kernel<<<(T_TR * 32 + 255) / 256, 256>>>(traces, lengths);
    gemv_partial_kernel<<<NB_D, 128>>>();
    finalize_kernel<<<1, 128>>>(Wout, bout, out);
}

// round 5
// speedup vs baseline: 3.5152x; 3.5152x over previous
#include <cuda_runtime.h>

// Problem constants
#define V_SZ   10000
#define IN_SZ  64
#define H_SZ   128
#define L_SEQ  64
#define T_TR   4096

#define NBLK   148                        // persistent-ish grid: 1 block/SM
#define ROWS_PB ((V_SZ + NBLK - 1) / NBLK) // 68 vocab rows per block
#define RB_A   8                          // layer1 rows per batch
#define RB_B   6                          // layer2 rows per batch
#define NB_D   625                        // gemv blocks (16 rows each)

// Scratch (no allocations allowed — __device__ globals)
__device__ float g_h1[V_SZ * H_SZ];        // per-vocab layer1 hidden
__device__ float g_h2[V_SZ * H_SZ];        // per-vocab hidden_out
__device__ float g_energy[V_SZ];           // per-vocab attention energy
__device__ float g_coeff[V_SZ];            // summed softmax weight per vocab
__device__ float g_partials[NB_D * H_SZ];  // GEMV partials

typedef unsigned long long u64;

// packed f32x2 FMA (sm_100+): 2 fp32 MACs per instruction
__device__ __forceinline__ u64 fma2(u64 a, u64 b, u64 c) {
    u64 d;
    asm("fma.rn.f32x2 %0, %1, %2, %3;" : "=l"(d) : "l"(a), "l"(b), "l"(c));
    return d;
}
__device__ __forceinline__ u64 pack2(float lo, float hi) {
    u64 d;
    asm("mov.b64 %0, {%1, %2};" : "=l"(d) : "f"(lo), "f"(hi));
    return d;
}
__device__ __forceinline__ float hsum2(u64 v) {
    float lo, hi;
    asm("mov.b64 {%0, %1}, %2;" : "=f"(lo), "=f"(hi) : "l"(v));
    return lo + hi;
}
// fast, accurate-enough (~1e-6) sigmoid / tanh via MUFU
__device__ __forceinline__ float sig_f(float x) {
    return __fdividef(1.0f, 1.0f + __expf(-x));
}
__device__ __forceinline__ float tanh_f(float x) {
    return 2.0f * sig_f(2.0f * x) - 1.0f;
}
// torch gate rows actually used: i -> [0,128), g(c_hat) -> [256,384), o -> [384,512)
__device__ __forceinline__ int gate_row(int gate, int h) {
    return (gate == 0 ? 0 : (gate == 1 ? 2 * H_SZ : 3 * H_SZ)) + h;
}

// ---------------------------------------------------------------------------
// Kernel 0: zero the coefficient scatter buffer (graph replays need this)
// ---------------------------------------------------------------------------
__global__ void zero_coeff_kernel() {
    int i = blockIdx.x * blockDim.x + threadIdx.x;
    if (i < V_SZ) g_coeff[i] = 0.0f;
}

// ---------------------------------------------------------------------------
// Kernel A: layer1 for all vocab rows. Weight-stationary:
// thread (gate,h) holds its 64-wide weight row in 32 packed-f32x2 registers,
// streams vocab rows (x broadcast from smem). Gates -> smem -> combine -> g_h1.
// ---------------------------------------------------------------------------
__global__ __launch_bounds__(384, 1) void layer1_kernel(
    const float* __restrict__ emb,
    const float* __restrict__ W1,
    const float* __restrict__ bi1, const float* __restrict__ bh1)
{
    __shared__ __align__(16) float s_w[384 * 17];          // weight staging (chunked)
    __shared__ __align__(16) float s_x[RB_A * IN_SZ];      // vocab rows
    __shared__ float s_gate[3][RB_A][H_SZ];                // pre-activations

    const int t = threadIdx.x;
    const int gate = t >> 7;
    const int h = t & 127;
    const int grow = gate_row(gate, h);
    const float bsum = bi1[grow] + bh1[grow];

    // --- fill weight registers via coalesced smem chunks (k-chunks of 16) ---
    u64 ww[32];
    #pragma unroll
    for (int c = 0; c < 4; c++) {
        for (int idx = t; idx < 384 * 16; idx += 384) {
            int rrow = idx >> 4, k = idx & 15;
            s_w[rrow * 17 + k] = W1[gate_row(rrow >> 7, rrow & 127) * IN_SZ + c * 16 + k];
        }
        __syncthreads();
        #pragma unroll
        for (int kk = 0; kk < 8; kk++)
            ww[c * 8 + kk] = pack2(s_w[t * 17 + 2 * kk], s_w[t * 17 + 2 * kk + 1]);
        __syncthreads();
    }

    const int vbeg = blockIdx.x * ROWS_PB;
    const int vend = min(vbeg + ROWS_PB, V_SZ);

    for (int vb = vbeg; vb < vend; vb += RB_A) {
        // stage x rows (coalesced)
        for (int idx = t; idx < RB_A * IN_SZ; idx += 384) {
            int v = vb + (idx >> 6);
            s_x[idx] = (v < V_SZ) ? emb[v * IN_SZ + (idx & 63)] : 0.0f;
        }
        __syncthreads();

        #pragma unroll
        for (int r = 0; r < RB_A; r++) {
            const ulonglong2* xp = (const ulonglong2*)&s_x[r * IN_SZ];
            u64 acc = 0;
            #pragma unroll
            for (int q = 0; q < 16; q++) {
                ulonglong2 xv = xp[q];             // broadcast LDS.128
                acc = fma2(ww[2 * q], xv.x, acc);
                acc = fma2(ww[2 * q + 1], xv.y, acc);
            }
            s_gate[gate][r][h] = hsum2(acc) + bsum;
        }
        __syncthreads();

        // combine gates -> h1 (coalesced store)
        for (int idx = t; idx < RB_A * H_SZ; idx += 384) {
            int r = idx >> 7, hh = idx & 127;
            int v = vb + r;
            if (v < V_SZ) {
                float c = sig_f(s_gate[0][r][hh]) * tanh_f(s_gate[1][r][hh]);
                g_h1[v * H_SZ + hh] = sig_f(s_gate[2][r][hh]) * tanh_f(c);
            }
        }
        __syncthreads();
    }
}

// ---------------------------------------------------------------------------
// Kernel B: layer2 (weight-stationary, 64 packed regs/thread) + attention
// energy (Wp1 pair-interleaved in smem, packed fma2).  Writes g_h2, g_energy.
// ---------------------------------------------------------------------------
__global__ __launch_bounds__(384, 1) void layer2_kernel(
    const float* __restrict__ W2,
    const float* __restrict__ bi2, const float* __restrict__ bh2,
    const float* __restrict__ Wp1, const float* __restrict__ bp1,
    const float* __restrict__ Wp2, const float* __restrict__ bp2)
{
    __shared__ __align__(16) float s_w[8192];              // chunk staging (6528) / Wp1 pair layout (8192)
    __shared__ __align__(16) float s_x[RB_B * H_SZ];       // h1 rows
    __shared__ __align__(16) float s_h2[RB_B][H_SZ];
    __shared__ float s_gate[3][RB_B][H_SZ];
    __shared__ float s_epart[RB_B][2];

    const int t = threadIdx.x;
    const int gate = t >> 7;
    const int h = t & 127;
    const int grow = gate_row(gate, h);
    const float bsum = bi2[grow] + bh2[grow];

    // --- fill weight registers (128-wide rows = 64 u64) ---
    u64 ww[64];
    #pragma unroll
    for (int c = 0; c < 8; c++) {
        for (int idx = t; idx < 384 * 16; idx += 384) {
            int rrow = idx >> 4, k = idx & 15;
            s_w[rrow * 17 + k] = W2[gate_row(rrow >> 7, rrow & 127) * H_SZ + c * 16 + k];
        }
        __syncthreads();
        #pragma unroll
        for (int kk = 0; kk < 8; kk++)
            ww[c * 8 + kk] = pack2(s_w[t * 17 + 2 * kk], s_w[t * 17 + 2 * kk + 1]);
        __syncthreads();
    }

    // --- stage Wp1 in pair-interleaved layout: s_w[k2*128 + u*2 + (k&1)] ---
    for (int idx = t; idx < 64 * H_SZ; idx += 384) {
        int u = idx >> 7, k = idx & 127;
        s_w[(k >> 1) * 128 + u * 2 + (k & 1)] = Wp1[idx];
    }
    __syncthreads();
    const u64* wp = (const u64*)s_w;   // element [k2*64 + u]

    const int uu = t & 63, grp = t >> 6;           // energy mapping
    const int vbeg = blockIdx.x * ROWS_PB;
    const int vend = min(vbeg + ROWS_PB, V_SZ);

    for (int vb = vbeg; vb < vend; vb += RB_B) {
        for (int idx = t; idx < RB_B * H_SZ; idx += 384) {
            int v = vb + (idx >> 7);
            s_x[idx] = (v < V_SZ) ? g_h1[v * H_SZ + (idx & 127)] : 0.0f;
        }
        __syncthreads();

        #pragma unroll
        for (int r = 0; r < RB_B; r++) {
            const ulonglong2* xp = (const ulonglong2*)&s_x[r * H_SZ];
            u64 acc = 0;
            #pragma unroll
            for (int q = 0; q < 32; q++) {
                ulonglong2 xv = xp[q];
                acc = fma2(ww[2 * q], xv.x, acc);
                acc = fma2(ww[2 * q + 1], xv.y, acc);
            }
            s_gate[gate][r][h] = hsum2(acc) + bsum;
        }
        __syncthreads();

        // combine -> h2 (smem + global)
        for (int idx = t; idx < RB_B * H_SZ; idx += 384) {
            int r = idx >> 7, hh = idx & 127;
            float c = sig_f(s_gate[0][r][hh]) * tanh_f(s_gate[1][r][hh]);
            float h2 = sig_f(s_gate[2][r][hh]) * tanh_f(c);
            s_h2[r][hh] = h2;
            int v = vb + r;
            if (v < V_SZ) g_h2[v * H_SZ + hh] = h2;
        }
        __syncthreads();

        // attention energy: thread (u=uu, row=grp), packed fma2
        {
            int r = grp;                 // grp in [0,6) == RB_B rows
            const ulonglong2* hp = (const ulonglong2*)&s_h2[r][0];
            u64 acc = 0;
            #pragma unroll
            for (int q = 0; q < 32; q++) {
                ulonglong2 hv = hp[q];
                acc = fma2(wp[(2 * q) * 64 + uu], hv.x, acc);
                acc = fma2(wp[(2 * q + 1) * 64 + uu], hv.y, acc);
            }
            float e = hsum2(acc) + bp1[uu];
            float s = fmaxf(e, 0.0f) * Wp2[uu];
            #pragma unroll
            for (int off = 16; off > 0; off >>= 1)
                s += __shfl_xor_sync(0xffffffffu, s, off);
            if ((t & 31) == 0) s_epart[r][(t >> 5) & 1] = s;
        }
        __syncthreads();
        if (t < RB_B) {
            int v = vb + t;
            if (v < V_SZ) g_energy[v] = s_epart[t][0] + s_epart[t][1] + bp2[0];
        }
        __syncthreads();
    }
}

// ---------------------------------------------------------------------------
// Kernel 2: per-trace softmax over gathered energies, scatter weights into
// per-vocab coefficients. One warp per trace (L=64 -> 2 positions per lane).
// ---------------------------------------------------------------------------
__global__ void softmax_scatter_kernel(const int* __restrict__ traces,
                                       const int* __restrict__ lengths)
{
    int gw   = (blockIdx.x * blockDim.x + threadIdx.x) >> 5;
    int lane = threadIdx.x & 31;
    if (gw >= T_TR) return;

    const int* tr = traces + gw * L_SEQ;
    int len = lengths[gw];
    int t0  = tr[lane];
    int t1  = tr[lane + 32];
    bool ok0 = lane < len;
    bool ok1 = (lane + 32) < len;

    float e0 = ok0 ? g_energy[t0] : -1e30f;
    float e1 = ok1 ? g_energy[t1] : -1e30f;

    float m = fmaxf(e0, e1);
    #pragma unroll
    for (int off = 16; off > 0; off >>= 1)
        m = fmaxf(m, __shfl_xor_sync(0xffffffffu, m, off));

    float x0 = ok0 ? __expf(e0 - m) : 0.0f;
    float x1 = ok1 ? __expf(e1 - m) : 0.0f;
    float s  = x0 + x1;
    #pragma unroll
    for (int off = 16; off > 0; off >>= 1)
        s += __shfl_xor_sync(0xffffffffu, s, off);

    float inv = 1.0f / s; // len >= 1 guarantees s > 0
    if (ok0) atomicAdd(&g_coeff[t0], x0 * inv);
    if (ok1) atomicAdd(&g_coeff[t1], x1 * inv);
}

// ---------------------------------------------------------------------------
// Kernel 3: partial GEMV  final[h] = sum_v coeff[v] * h2[v][h]
// 625 blocks x 16 rows, float4 loads, 4-deep MLP, smem cross-warp reduce.
// ---------------------------------------------------------------------------
__global__ __launch_bounds__(128) void gemv_partial_kernel() {
    __shared__ float red[4][H_SZ];
    int b = blockIdx.x, t = threadIdx.x;
    int w = t >> 5, lane = t & 31;
    float4 acc = make_float4(0.f, 0.f, 0.f, 0.f);
    int v0 = b * 16 + w * 4;
    #pragma unroll
    for (int i = 0; i < 4; i++) {
        int v = v0 + i;
        float c = g_coeff[v];
        float4 hv = *(const float4*)&g_h2[v * H_SZ + lane * 4];
        acc.x = fmaf(c, hv.x, acc.x);
        acc.y = fmaf(c, hv.y, acc.y);
        acc.z = fmaf(c, hv.z, acc.z);
        acc.w = fmaf(c, hv.w, acc.w);
    }
    *(float4*)&red[w][lane * 4] = acc;
    __syncthreads();
    g_partials[b * H_SZ + t] = red[0][t] + red[1][t] + red[2][t] + red[3][t];
}

// ---------------------------------------------------------------------------
// Kernel 4: reduce partials + output linear layer
// ---------------------------------------------------------------------------
__global__ __launch_bounds__(128) void finalize_kernel(
    const float* __restrict__ W_out, const float* __restrict__ b_out,
    float* __restrict__ out)
{
    __shared__ float fin[H_SZ];
    int tid = threadIdx.x;
    float f = 0.0f;
    #pragma unroll 5
    for (int b = 0; b < NB_D; b++) f += g_partials[b * H_SZ + tid];
    fin[tid] = f;
    __syncthreads();

    float o = b_out[tid];
    const float* wr = W_out + tid * H_SZ;
    #pragma unroll 8
    for (int k = 0; k < H_SZ; k++) o = fmaf(wr[k], fin[k], o);
    out[tid] = o;
}

// ---------------------------------------------------------------------------
// Launch: inputs per metadata order:
// 0 emb, 1 W_ih1, 2 W_hh1, 3 b_ih1, 4 b_hh1, 5 W_ih2, 6 W_hh2, 7 b_ih2,
// 8 b_hh2, 9 Wp1, 10 bp1, 11 Wp2, 12 bp2, 13 W_out, 14 b_out,
// 15 traces(int32), 16 lengths(int32)
// ---------------------------------------------------------------------------
extern "C" void kernel_launch(void* const* d_in, const int* in_sizes, int n_in,
                              void* d_out, int out_size)
{
    const float* emb   = (const float*)d_in[0];
    const float* W1    = (const float*)d_in[1];
    const float* bi1   = (const float*)d_in[3];
    const float* bh1   = (const float*)d_in[4];
    const float* W2    = (const float*)d_in[5];
    const float* bi2   = (const float*)d_in[7];
    const float* bh2   = (const float*)d_in[8];
    const float* Wp1   = (const float*)d_in[9];
    const float* bp1   = (const float*)d_in[10];
    const float* Wp2   = (const float*)d_in[11];
    const float* bp2   = (const float*)d_in[12];
    const float* Wout  = (const float*)d_in[13];
    const float* bout  = (const float*)d_in[14];
    const int* traces  = (const int*)d_in[15];
    const int* lengths = (const int*)d_in[16];
    float* out = (float*)d_out;

    zero_coeff_kernel<<<(V_SZ + 255) / 256, 256>>>();
    layer1_kernel<<<NBLK, 384>>>(emb, W1, bi1, bh1);
    layer2_kernel<<<NBLK, 384>>>(W2, bi2, bh2, Wp1, bp1, Wp2, bp2);
    softmax_scatter_kernel<<<(T_TR * 32 + 255) / 256, 256>>>(traces, lengths);
    gemv_partial_kernel<<<NB_D, 128>>>();
    finalize_kernel<<<1, 128>>>(Wout, bout, out);
}